// round 16
// baseline (speedup 1.0000x reference)
#include <cuda_runtime.h>
#include <cstdint>

// Problem constants
#define NB 4
#define TT 2048
#define DD 512
#define HH 8
#define HDIM 64
#define MROWS (NB * TT)   // 8192

// Scratch (allocation-free: __device__ globals)
__device__ float g_keys[NB * TT * DD];   // [n][tok][h*64+d], tf32-RNE
__device__ float g_vals[NB * TT * DD];   // TRANSPOSED [(n*512+h*64+d)][tok], tf32-RNE
__device__ float g_attn[NB * TT * DD];   // tf32-RNE (flash epilogue rounds)
__device__ float g_qtf [NB * TT * DD];   // tf32-RNE q
__device__ float g_wk  [DD * DD];
__device__ float g_wv  [DD * DD];
__device__ float g_wo  [DD * DD];

// ---------------------------------------------------------------------------
// Helpers
// ---------------------------------------------------------------------------
__device__ __forceinline__ unsigned f2tf(float x) {
    unsigned r;
    asm("cvt.rna.tf32.f32 %0, %1;" : "=r"(r) : "f"(x));
    return r;
}
__device__ __forceinline__ float f2tf_f(float x) { return __uint_as_float(f2tf(x)); }

__device__ __forceinline__ float ex2f(float x) {
    float y;
    asm("ex2.approx.ftz.f32 %0, %1;" : "=f"(y) : "f"(x));
    return y;
}

__device__ __forceinline__ void mma_tf32(float& c0, float& c1, float& c2, float& c3,
                                         unsigned a0, unsigned a1, unsigned a2, unsigned a3,
                                         unsigned b0, unsigned b1) {
    asm volatile(
        "mma.sync.aligned.m16n8k8.row.col.f32.tf32.tf32.f32 "
        "{%0,%1,%2,%3}, {%4,%5,%6,%7}, {%8,%9}, {%0,%1,%2,%3};"
        : "+f"(c0), "+f"(c1), "+f"(c2), "+f"(c3)
        : "r"(a0), "r"(a1), "r"(a2), "r"(a3), "r"(b0), "r"(b1));
}

__device__ __forceinline__ void cp_async16(unsigned saddr, const void* gptr) {
    asm volatile("cp.async.cg.shared.global [%0], [%1], 16;" :: "r"(saddr), "l"(gptr));
}

__device__ __forceinline__ void ldsm_x4(unsigned& r0, unsigned& r1, unsigned& r2, unsigned& r3,
                                        uint32_t addr) {
    asm volatile("ldmatrix.sync.aligned.m8n8.x4.shared.b16 {%0,%1,%2,%3}, [%4];"
                 : "=r"(r0), "=r"(r1), "=r"(r2), "=r"(r3) : "r"(addr));
}

__device__ __forceinline__ uint32_t smem_u32(const void* p) {
    return (uint32_t)__cvta_generic_to_shared(p);
}

// ---------------------------------------------------------------------------
// Prep: elementwise tf32-RNE rounding pass
// ---------------------------------------------------------------------------
__global__ void round_tf32(const float* __restrict__ src, float* __restrict__ dst, int n4) {
    int i = blockIdx.x * blockDim.x + threadIdx.x;
    if (i < n4) {
        float4 v = ((const float4*)src)[i];
        ((float4*)dst)[i] = make_float4(f2tf_f(v.x), f2tf_f(v.y), f2tf_f(v.z), f2tf_f(v.w));
    }
}

// ---------------------------------------------------------------------------
// Tensor-core GEMM NT, cp.async 2-stage + ldmatrix fragments.
// C = A @ B^T (+ fp32 residual R). Inputs A,B pre-rounded tf32 (raw bytes).
// BM=BN=128, BK=32, 8 warps (4M x 2N). TRANSP: scatter transposed vals.
// ---------------------------------------------------------------------------
#define GSTR 36
#define STG_FLOATS (128 * GSTR)            // 4608
#define STG_BYTES (STG_FLOATS * 4)         // 18432
#define GEMM_DB_SMEM (4 * STG_BYTES)       // 73728

template <bool RESIDUAL, bool TF32OUT, bool TRANSP>
__global__ __launch_bounds__(256, 2) void tgemm_db(const float* __restrict__ A,
                                                   const float* __restrict__ B,
                                                   const float* __restrict__ R,
                                                   float* __restrict__ C) {
    constexpr int BK = 32, NKT_G = DD / BK;   // 16
    extern __shared__ float gsm[];
    const uint32_t base = smem_u32(gsm);
    const uint32_t abase[2] = {base, base + STG_BYTES};
    const uint32_t bbase[2] = {base + 2 * STG_BYTES, base + 3 * STG_BYTES};

    const int tid  = threadIdx.x;
    const int lane = tid & 31;
    const int wid  = tid >> 5;
    const int l4   = lane & 3;
    const int g    = lane >> 2;
    const int wm   = (wid & 3) * 32;
    const int wn   = (wid >> 2) * 64;
    const int bm   = blockIdx.x * 128;
    const int bn   = blockIdx.y * 128;

    // ldmatrix lane-relative offsets (bytes), same proven mappings as R15.
    const int mrow = lane & 7;
    const int mh   = lane >> 3;
    uint32_t arel[2];
#pragma unroll
    for (int mt = 0; mt < 2; mt++)
        arel[mt] = (uint32_t)(((wm + mt * 16 + mrow + (mh & 1) * 8) * GSTR + 4 * (mh >> 1)) * 4);
    uint32_t brel[4];
#pragma unroll
    for (int j = 0; j < 4; j++)
        brel[j] = (uint32_t)(((wn + (2 * j + (mh >> 1)) * 8 + mrow) * GSTR + 4 * (mh & 1)) * 4);

    float c[2][8][4];
#pragma unroll
    for (int mt = 0; mt < 2; mt++)
#pragma unroll
        for (int nt = 0; nt < 8; nt++)
#pragma unroll
            for (int j = 0; j < 4; j++) c[mt][nt][j] = 0.f;

    auto issue = [&](int kt, int s) {
        const int k0 = kt * BK;
#pragma unroll
        for (int it = 0; it < 4; it++) {
            int i  = tid + it * 256;       // 0..1023
            int r  = i >> 3;               // 0..127
            int c4 = (i & 7) << 2;         // 0..28
            uint32_t off = (uint32_t)(r * GSTR + c4) * 4u;
            cp_async16(abase[s] + off, A + (size_t)(bm + r) * DD + k0 + c4);
            cp_async16(bbase[s] + off, B + (size_t)(bn + r) * DD + k0 + c4);
        }
        asm volatile("cp.async.commit_group;");
    };

    issue(0, 0);

    for (int kt = 0; kt < NKT_G; kt++) {
        const int s = kt & 1;
        if (kt + 1 < NKT_G) {
            issue(kt + 1, s ^ 1);            // buffer s^1 free (trailing sync of kt-1)
            asm volatile("cp.async.wait_group 1;");
        } else {
            asm volatile("cp.async.wait_group 0;");
        }
        __syncthreads();                     // stage s visible to all warps

#pragma unroll
        for (int k8 = 0; k8 < BK / 8; k8++) {
            unsigned a[2][4];
#pragma unroll
            for (int mt = 0; mt < 2; mt++)
                ldsm_x4(a[mt][0], a[mt][1], a[mt][2], a[mt][3],
                        abase[s] + arel[mt] + k8 * 32);
            unsigned b0[8], b1[8];
#pragma unroll
            for (int j = 0; j < 4; j++)
                ldsm_x4(b0[2 * j], b1[2 * j], b0[2 * j + 1], b1[2 * j + 1],
                        bbase[s] + brel[j] + k8 * 32);
#pragma unroll
            for (int nt = 0; nt < 8; nt++) {
                mma_tf32(c[0][nt][0], c[0][nt][1], c[0][nt][2], c[0][nt][3],
                         a[0][0], a[0][1], a[0][2], a[0][3], b0[nt], b1[nt]);
                mma_tf32(c[1][nt][0], c[1][nt][1], c[1][nt][2], c[1][nt][3],
                         a[1][0], a[1][1], a[1][2], a[1][3], b0[nt], b1[nt]);
            }
        }
        __syncthreads();                     // stage s consumed before reuse
    }

#pragma unroll
    for (int mt = 0; mt < 2; mt++) {
        int r1 = bm + wm + mt * 16 + g;
        int r2 = r1 + 8;
#pragma unroll
        for (int nt = 0; nt < 8; nt++) {
            int col = bn + wn + nt * 8 + 2 * l4;
            float2 v1 = make_float2(c[mt][nt][0], c[mt][nt][1]);
            float2 v2 = make_float2(c[mt][nt][2], c[mt][nt][3]);
            if (RESIDUAL) {
                float2 q1 = *(const float2*)(R + (size_t)r1 * DD + col);
                float2 q2 = *(const float2*)(R + (size_t)r2 * DD + col);
                v1.x += q1.x; v1.y += q1.y;
                v2.x += q2.x; v2.y += q2.y;
            }
            if (TF32OUT) {
                v1.x = f2tf_f(v1.x); v1.y = f2tf_f(v1.y);
                v2.x = f2tf_f(v2.x); v2.y = f2tf_f(v2.y);
            }
            if (TRANSP) {
                size_t b1a = ((size_t)(r1 >> 11) * 512 + col) * TT + (r1 & 2047);
                size_t b2a = ((size_t)(r2 >> 11) * 512 + col) * TT + (r2 & 2047);
                C[b1a]      = v1.x;
                C[b1a + TT] = v1.y;
                C[b2a]      = v2.x;
                C[b2a + TT] = v2.y;
            } else {
                *(float2*)(C + (size_t)r1 * DD + col) = v1;
                *(float2*)(C + (size_t)r2 * DD + col) = v2;
            }
        }
    }
}

// ---------------------------------------------------------------------------
// Flash attention, tf32 mma.sync + ldmatrix. Proven R15; epilogue now rounds
// attn to tf32 (Wo GEMM consumes raw bytes).
// ---------------------------------------------------------------------------
#define BQ 128
#define BKV 64
#define FSTR 68
#define NKT (TT / BKV)   // 32 KV tiles

#define FLASH_SMEM_FLOATS (FSTR * (BQ + 4 * BKV))
#define FLASH_SMEM_BYTES (FLASH_SMEM_FLOATS * 4)

__global__ __launch_bounds__(256, 2) void flash_attn_tc(const float* __restrict__ Q) {
    extern __shared__ float sm[];
    float* Qp  = sm;
    float* Ks0 = Qp  + BQ  * FSTR;
    float* Ks1 = Ks0 + BKV * FSTR;
    float* Vs0 = Ks1 + BKV * FSTR;
    float* Vs1 = Vs0 + BKV * FSTR;

    const unsigned ks0u = smem_u32(Ks0);
    const unsigned ks1u = smem_u32(Ks1);
    const unsigned vs0u = smem_u32(Vs0);
    const unsigned vs1u = smem_u32(Vs1);
    const unsigned qpu  = smem_u32(Qp);

    const int tid  = threadIdx.x;
    const int lane = tid & 31;
    const int wid  = tid >> 5;
    const int l4   = lane & 3;
    const int g    = lane >> 2;
    const int wb   = wid * 16;

    const int qt = blockIdx.x;
    const int nh = blockIdx.y;
    const int n  = nh >> 3;
    const int h  = nh & 7;

    const float* Qbase = Q      + (size_t)n * TT * DD + (size_t)(qt * BQ) * DD + h * HDIM;
    const float* Kbase = g_keys + (size_t)n * TT * DD + h * HDIM;
    const float* Vtb   = g_vals + ((size_t)n * 512 + h * HDIM) * TT;

    const int mrow = lane & 7;
    const int mh   = lane >> 3;
    unsigned kvoff[4];
#pragma unroll
    for (int j = 0; j < 4; j++)
        kvoff[j] = (unsigned)((((2 * j + (mh >> 1)) * 8 + mrow) * FSTR + 4 * (mh & 1)) * 4);
    const unsigned poff =
        (unsigned)(((wb + mrow + (mh & 1) * 8) * FSTR + 4 * (mh >> 1)) * 4);

    const float QSCALE = 0.125f * 1.44269504088896341f;
    for (int i = tid; i < BQ * 16; i += 256) {
        int r = i >> 4, d4 = (i & 15) << 2;
        float4 v = *(const float4*)(Qbase + (size_t)r * DD + d4);
        *(float4*)&Qp[r * FSTR + d4] =
            make_float4(f2tf_f(v.x * QSCALE), f2tf_f(v.y * QSCALE),
                        f2tf_f(v.z * QSCALE), f2tf_f(v.w * QSCALE));
    }

#pragma unroll
    for (int it = 0; it < 4; it++) {
        int i = tid + it * 256;
        int r = i >> 4, c4 = (i & 15) << 2;
        unsigned off = (unsigned)(r * FSTR + c4) * 4u;
        cp_async16(ks0u + off, Kbase + (size_t)r * DD + c4);
        cp_async16(vs0u + off, Vtb + (size_t)r * TT + c4);
    }
    asm volatile("cp.async.commit_group;");

    __syncthreads();

    unsigned qf[8][4];
#pragma unroll
    for (int k = 0; k < 8; k++)
        ldsm_x4(qf[k][0], qf[k][1], qf[k][2], qf[k][3], qpu + poff + k * 32);

    float m1 = -1e30f, m2 = -1e30f, l1 = 0.f, l2 = 0.f;
    float oc[8][4];
#pragma unroll
    for (int nt = 0; nt < 8; nt++)
#pragma unroll
        for (int j = 0; j < 4; j++) oc[nt][j] = 0.f;

    for (int kt = 0; kt < NKT; kt++) {
        const bool odd = kt & 1;
        const unsigned kc = odd ? ks1u : ks0u;
        const unsigned vc = odd ? vs1u : vs0u;

        asm volatile("cp.async.wait_group 0;");
        __syncthreads();

        if (kt + 1 < NKT) {
            unsigned knu = odd ? ks0u : ks1u;
            unsigned vnu = odd ? vs0u : vs1u;
            const float* Kt = Kbase + (size_t)((kt + 1) * BKV) * DD;
            const float* Vt = Vtb + (kt + 1) * BKV;
#pragma unroll
            for (int it = 0; it < 4; it++) {
                int i = tid + it * 256;
                int r = i >> 4, c4 = (i & 15) << 2;
                unsigned off = (unsigned)(r * FSTR + c4) * 4u;
                cp_async16(knu + off, Kt + (size_t)r * DD + c4);
                cp_async16(vnu + off, Vt + (size_t)r * TT + c4);
            }
            asm volatile("cp.async.commit_group;");
        }

        float sc[8][4];
#pragma unroll
        for (int nt = 0; nt < 8; nt++)
#pragma unroll
            for (int j = 0; j < 4; j++) sc[nt][j] = 0.f;

#pragma unroll
        for (int k = 0; k < 8; k++) {
            unsigned kb0[8], kb1[8];
#pragma unroll
            for (int j = 0; j < 4; j++)
                ldsm_x4(kb0[2 * j], kb1[2 * j], kb0[2 * j + 1], kb1[2 * j + 1],
                        kc + kvoff[j] + k * 32);
#pragma unroll
            for (int nt = 0; nt < 8; nt++)
                mma_tf32(sc[nt][0], sc[nt][1], sc[nt][2], sc[nt][3],
                         qf[k][0], qf[k][1], qf[k][2], qf[k][3], kb0[nt], kb1[nt]);
        }

        float rmax1 = -1e30f, rmax2 = -1e30f;
#pragma unroll
        for (int nt = 0; nt < 8; nt++) {
            rmax1 = fmaxf(rmax1, fmaxf(sc[nt][0], sc[nt][1]));
            rmax2 = fmaxf(rmax2, fmaxf(sc[nt][2], sc[nt][3]));
        }
        rmax1 = fmaxf(rmax1, __shfl_xor_sync(0xffffffffu, rmax1, 1, 4));
        rmax1 = fmaxf(rmax1, __shfl_xor_sync(0xffffffffu, rmax1, 2, 4));
        rmax2 = fmaxf(rmax2, __shfl_xor_sync(0xffffffffu, rmax2, 1, 4));
        rmax2 = fmaxf(rmax2, __shfl_xor_sync(0xffffffffu, rmax2, 2, 4));

        float mn1 = fmaxf(m1, rmax1), mn2 = fmaxf(m2, rmax2);
        float corr1 = ex2f(m1 - mn1), corr2 = ex2f(m2 - mn2);

        float sum1 = 0.f, sum2 = 0.f;
#pragma unroll
        for (int nt = 0; nt < 8; nt++) {
            float p0 = ex2f(sc[nt][0] - mn1);
            float p1 = ex2f(sc[nt][1] - mn1);
            float p2 = ex2f(sc[nt][2] - mn2);
            float p3 = ex2f(sc[nt][3] - mn2);
            sum1 += p0 + p1;
            sum2 += p2 + p3;
            *(float2*)&Qp[(wb + g) * FSTR + nt * 8 + 2 * l4] =
                make_float2(f2tf_f(p0), f2tf_f(p1));
            *(float2*)&Qp[(wb + g + 8) * FSTR + nt * 8 + 2 * l4] =
                make_float2(f2tf_f(p2), f2tf_f(p3));
        }
        sum1 += __shfl_xor_sync(0xffffffffu, sum1, 1, 4);
        sum1 += __shfl_xor_sync(0xffffffffu, sum1, 2, 4);
        sum2 += __shfl_xor_sync(0xffffffffu, sum2, 1, 4);
        sum2 += __shfl_xor_sync(0xffffffffu, sum2, 2, 4);

        l1 = l1 * corr1 + sum1;  m1 = mn1;
        l2 = l2 * corr2 + sum2;  m2 = mn2;
#pragma unroll
        for (int nt = 0; nt < 8; nt++) {
            oc[nt][0] *= corr1; oc[nt][1] *= corr1;
            oc[nt][2] *= corr2; oc[nt][3] *= corr2;
        }

        __syncwarp();

#pragma unroll
        for (int k = 0; k < 8; k++) {
            unsigned pa[4];
            ldsm_x4(pa[0], pa[1], pa[2], pa[3], qpu + poff + k * 32);
            unsigned vb0[8], vb1[8];
#pragma unroll
            for (int j = 0; j < 4; j++)
                ldsm_x4(vb0[2 * j], vb1[2 * j], vb0[2 * j + 1], vb1[2 * j + 1],
                        vc + kvoff[j] + k * 32);
#pragma unroll
            for (int nt = 0; nt < 8; nt++)
                mma_tf32(oc[nt][0], oc[nt][1], oc[nt][2], oc[nt][3],
                         pa[0], pa[1], pa[2], pa[3], vb0[nt], vb1[nt]);
        }
    }

    float inv1 = 1.0f / l1, inv2 = 1.0f / l2;
    float* Ob = g_attn + (size_t)n * TT * DD + (size_t)(qt * BQ) * DD + h * HDIM;
#pragma unroll
    for (int nt = 0; nt < 8; nt++) {
        *(float2*)&Ob[(size_t)(wb + g) * DD + nt * 8 + 2 * l4] =
            make_float2(f2tf_f(oc[nt][0] * inv1), f2tf_f(oc[nt][1] * inv1));
        *(float2*)&Ob[(size_t)(wb + g + 8) * DD + nt * 8 + 2 * l4] =
            make_float2(f2tf_f(oc[nt][2] * inv2), f2tf_f(oc[nt][3] * inv2));
    }
}

// ---------------------------------------------------------------------------
// Launch
// ---------------------------------------------------------------------------
extern "C" void kernel_launch(void* const* d_in, const int* in_sizes, int n_in,
                              void* d_out, int out_size) {
    const float* q  = (const float*)d_in[0];
    const float* Wk = (const float*)d_in[1];
    const float* Wv = (const float*)d_in[2];
    const float* Wo = (const float*)d_in[3];
    float* out = (float*)d_out;

    float *keys, *vals, *attn, *qtf, *wk, *wv, *wo;
    cudaGetSymbolAddress((void**)&keys, g_keys);
    cudaGetSymbolAddress((void**)&vals, g_vals);
    cudaGetSymbolAddress((void**)&attn, g_attn);
    cudaGetSymbolAddress((void**)&qtf,  g_qtf);
    cudaGetSymbolAddress((void**)&wk,   g_wk);
    cudaGetSymbolAddress((void**)&wv,   g_wv);
    cudaGetSymbolAddress((void**)&wo,   g_wo);

    // Pre-round inputs to tf32 RNE (GEMMs cp.async raw bytes).
    const int nq4 = MROWS * DD / 4;
    const int nw4 = DD * DD / 4;
    round_tf32<<<(nq4 + 255) / 256, 256>>>(q,  qtf, nq4);
    round_tf32<<<(nw4 + 255) / 256, 256>>>(Wk, wk,  nw4);
    round_tf32<<<(nw4 + 255) / 256, 256>>>(Wv, wv,  nw4);
    round_tf32<<<(nw4 + 255) / 256, 256>>>(Wo, wo,  nw4);

    dim3 gGemm(MROWS / 128, DD / 128);   // (64, 4)
    cudaFuncSetAttribute(tgemm_db<true , true , false>, cudaFuncAttributeMaxDynamicSharedMemorySize, GEMM_DB_SMEM);
    cudaFuncSetAttribute(tgemm_db<false, true , true >, cudaFuncAttributeMaxDynamicSharedMemorySize, GEMM_DB_SMEM);
    cudaFuncSetAttribute(tgemm_db<false, false, false>, cudaFuncAttributeMaxDynamicSharedMemorySize, GEMM_DB_SMEM);

    // keys = tf32(qtf @ wk^T + q) ; vals = tf32(qtf @ wv^T) stored TRANSPOSED
    tgemm_db<true , true , false><<<gGemm, 256, GEMM_DB_SMEM>>>(qtf, wk, q, keys);
    tgemm_db<false, true , true ><<<gGemm, 256, GEMM_DB_SMEM>>>(qtf, wv, nullptr, vals);

    // flash attention (tf32 mma.sync + ldmatrix, cp.async double-buffered)
    cudaFuncSetAttribute(flash_attn_tc, cudaFuncAttributeMaxDynamicSharedMemorySize,
                         FLASH_SMEM_BYTES);
    dim3 gFlash(TT / BQ, NB * HH);       // (16, 32)
    flash_attn_tc<<<gFlash, 256, FLASH_SMEM_BYTES>>>(q);

    // out = attn(tf32) @ wo^T   (fp32 output)
    tgemm_db<false, false, false><<<gGemm, 256, GEMM_DB_SMEM>>>(attn, wo, nullptr, out);
}